// round 1
// baseline (speedup 1.0000x reference)
#include <cuda_runtime.h>
#include <math.h>

// mParametricLIF: x [N=128, T=64, D=4096] f32 -> spikes [N,T,D] f32.
// Per-(n,d) recurrence over t:
//   m = lam*m + k*(x - v);  v += m;  s = (v >= th);  v *= (1-s);  out = s
// k = sigmoid(tau_param[0]), lam = lamb[0], th = th[0].
//
// One thread owns 4 contiguous d (float4 lane), scans all T.
// t-loop unrolled by 8 to batch independent LDG.128 (MLP) ahead of the
// serial recurrence math.

#ifndef TUNROLL
#define TUNROLL 8
#endif

__global__ __launch_bounds__(256) void mplif_kernel(
    const float4* __restrict__ x4,
    const float* __restrict__ tau_param,
    const float* __restrict__ lamb,
    const float* __restrict__ thr,
    float4* __restrict__ out4,
    int T, int DC /* D/4 */, int lanes /* N*DC */)
{
    int tid = blockIdx.x * blockDim.x + threadIdx.x;
    if (tid >= lanes) return;

    int n = tid / DC;
    int c = tid - n * DC;
    long base = (long)n * T * DC + c;

    const float k   = 1.0f / (1.0f + expf(-tau_param[0]));
    const float lam = lamb[0];
    const float th  = thr[0];

    float4 v = make_float4(0.f, 0.f, 0.f, 0.f);
    float4 m = make_float4(0.f, 0.f, 0.f, 0.f);

    float4 buf[TUNROLL];

    for (int t0 = 0; t0 < T; t0 += TUNROLL) {
        // Batch independent loads first (MLP).
        #pragma unroll
        for (int j = 0; j < TUNROLL; j++) {
            buf[j] = x4[base + (long)(t0 + j) * DC];
        }
        // Serial recurrence on registers.
        #pragma unroll
        for (int j = 0; j < TUNROLL; j++) {
            float4 xv = buf[j];
            float4 s;

            m.x = lam * m.x + k * (xv.x - v.x); v.x += m.x;
            m.y = lam * m.y + k * (xv.y - v.y); v.y += m.y;
            m.z = lam * m.z + k * (xv.z - v.z); v.z += m.z;
            m.w = lam * m.w + k * (xv.w - v.w); v.w += m.w;

            s.x = (v.x >= th) ? 1.0f : 0.0f;
            s.y = (v.y >= th) ? 1.0f : 0.0f;
            s.z = (v.z >= th) ? 1.0f : 0.0f;
            s.w = (v.w >= th) ? 1.0f : 0.0f;

            v.x = (s.x != 0.0f) ? 0.0f : v.x;
            v.y = (s.y != 0.0f) ? 0.0f : v.y;
            v.z = (s.z != 0.0f) ? 0.0f : v.z;
            v.w = (s.w != 0.0f) ? 0.0f : v.w;

            out4[base + (long)(t0 + j) * DC] = s;
        }
    }
}

extern "C" void kernel_launch(void* const* d_in, const int* in_sizes, int n_in,
                              void* d_out, int out_size)
{
    const float* x         = (const float*)d_in[0];
    const float* tau_param = (const float*)d_in[1];
    const float* lamb      = (const float*)d_in[2];
    const float* th        = (const float*)d_in[3];
    float* out             = (float*)d_out;

    const int N = 128, T = 64, D = 4096;
    const int DC = D / 4;
    const int lanes = N * DC;

    dim3 block(256);
    dim3 grid((lanes + block.x - 1) / block.x);
    mplif_kernel<<<grid, block>>>((const float4*)x, tau_param, lamb, th,
                                  (float4*)out, T, DC, lanes);
}